// round 1
// baseline (speedup 1.0000x reference)
#include <cuda_runtime.h>
#include <cuda_bf16.h>

#define EMB 32
#define K 10
#define NPB 128      // nodes per block
#define THREADS 128

// 64 MB scratch for layer-1 hidden embeddings (allowed: __device__ global)
__device__ float g_h1[500000 * EMB];

__global__ __launch_bounds__(THREADS)
void sage_layer_kernel(const float* __restrict__ feat,      // [Nf, 32] source features
                       const int*   __restrict__ node_ids,  // [n] or nullptr (identity)
                       const int*   __restrict__ neigh,     // [N_NODES, K]
                       const float* __restrict__ W,         // [32, 64] row-major
                       float*       __restrict__ out,       // [n, 32]
                       int n)
{
    __shared__ __align__(16) float Ws[32 * 64];   // 8 KB
    __shared__ float comb[NPB][65];               // 33.3 KB, padded vs bank conflicts
    __shared__ int   snid[NPB];                   // node ids for this block
    __shared__ int   snb[NPB * K];                // neighbor ids

    const int tid  = threadIdx.x;
    const int base = blockIdx.x * NPB;

    // ---- load W into shared (coalesced) ----
    #pragma unroll
    for (int x = tid; x < 32 * 64; x += THREADS)
        Ws[x] = W[x];

    // ---- node ids ----
    if (tid < NPB) {
        int g = base + tid;
        snid[tid] = (g < n) ? (node_ids ? node_ids[g] : g) : 0;
    }
    __syncthreads();

    // ---- neighbor id gather into shared ----
    for (int x = tid; x < NPB * K; x += THREADS) {
        int nd = x / K;
        int k  = x - nd * K;
        snb[x] = neigh[snid[nd] * K + k];
    }

    // ---- self features: one warp per 128B row, coalesced ----
    for (int x = tid; x < NPB * EMB; x += THREADS) {
        int nd = x >> 5, d = x & 31;
        comb[nd][d] = feat[snid[nd] * EMB + d];
    }
    __syncthreads();   // snb ready for all threads

    // ---- mean aggregation: warp reads one 128B neighbor row per k, coalesced ----
    for (int x = tid; x < NPB * EMB; x += THREADS) {
        int nd = x >> 5, d = x & 31;
        float s = 0.f;
        #pragma unroll
        for (int k = 0; k < K; k++)
            s += feat[snb[nd * K + k] * EMB + d];
        comb[nd][EMB + d] = s * 0.1f;
    }
    __syncthreads();

    // ---- phase B: thread t computes node t's 32 outputs ----
    // Read own combined row into registers (bank-conflict-free via pad-65).
    float rc[64];
    #pragma unroll
    for (int i = 0; i < 64; i++)
        rc[i] = comb[tid][i];

    const float4* Wv = reinterpret_cast<const float4*>(Ws);
    // Each thread only reads/writes its own comb row from here on -> no sync needed.
    #pragma unroll 4
    for (int j = 0; j < 32; j++) {
        float acc = 0.f;
        #pragma unroll
        for (int i4 = 0; i4 < 16; i4++) {
            float4 w = Wv[j * 16 + i4];   // uniform address: LDS.128 broadcast
            acc = fmaf(rc[4 * i4 + 0], w.x, acc);
            acc = fmaf(rc[4 * i4 + 1], w.y, acc);
            acc = fmaf(rc[4 * i4 + 2], w.z, acc);
            acc = fmaf(rc[4 * i4 + 3], w.w, acc);
        }
        comb[tid][j] = fmaxf(acc, 0.f);   // ReLU, staged for coalesced store
    }
    __syncthreads();

    // ---- coalesced store: output row = batch position (base + nd) ----
    for (int x = tid; x < NPB * EMB; x += THREADS) {
        int nd = x >> 5, d = x & 31;
        int g = base + nd;
        if (g < n)
            out[g * EMB + d] = comb[nd][d];
    }
}

extern "C" void kernel_launch(void* const* d_in, const int* in_sizes, int n_in,
                              void* d_out, int out_size)
{
    // metadata order: emb, W1, W2, node_batch, neigh
    const float* emb        = (const float*)d_in[0];
    const float* W1         = (const float*)d_in[1];
    const float* W2         = (const float*)d_in[2];
    const int*   node_batch = (const int*)  d_in[3];
    const int*   neigh      = (const int*)  d_in[4];
    float*       out        = (float*)d_out;

    const int N = in_sizes[0] / EMB;   // 500000
    const int B = in_sizes[3];         // 100000

    float* h1 = nullptr;
    cudaGetSymbolAddress((void**)&h1, g_h1);

    // Layer 1: h1 = relu([emb | mean(emb[neigh])] @ W1^T) for all nodes
    sage_layer_kernel<<<(N + NPB - 1) / NPB, THREADS>>>(emb, nullptr, neigh, W1, h1, N);
    // Layer 2: out = relu([h1[nb] | mean(h1[neigh[nb]])] @ W2^T) for batch nodes
    sage_layer_kernel<<<(B + NPB - 1) / NPB, THREADS>>>(h1, node_batch, neigh, W2, out, B);
}

// round 2
// speedup vs baseline: 1.1373x; 1.1373x over previous
#include <cuda_runtime.h>
#include <cuda_bf16.h>

#define EMB 32
#define K 10
#define NPB 128      // nodes per block
#define THREADS 128
#define PITCH 36     // comb row pitch (floats): 16B-aligned rows, conflict floor only

// 64 MB scratch for layer-1 hidden embeddings (allowed: __device__ global)
__device__ float g_h1[500000 * EMB];

__global__ __launch_bounds__(THREADS, 6)
void sage_layer_kernel(const float* __restrict__ feat,      // [Nf, 32] source features
                       const int*   __restrict__ node_ids,  // [n] or nullptr (identity)
                       const int*   __restrict__ neigh,     // [N_NODES, K]
                       const float* __restrict__ W,         // [32, 64] row-major
                       float*       __restrict__ out,       // [n, 32]
                       int n)
{
    __shared__ __align__(16) float Ws[32 * 64];        // 8 KB
    __shared__ __align__(16) float comb[NPB][PITCH];   // 18.4 KB, reused: self then agg
    __shared__ int snid[NPB];                          // 0.5 KB

    const int tid  = threadIdx.x;
    const int lane = tid & 31;
    const int wrp  = tid >> 5;
    const int base = blockIdx.x * NPB;

    // ---- W into shared (coalesced) ----
    #pragma unroll
    for (int x = tid; x < 32 * 64; x += THREADS)
        Ws[x] = W[x];

    // ---- node ids ----
    if (tid < NPB) {
        int g = base + tid;
        snid[tid] = (g < n) ? (node_ids ? node_ids[g] : g) : 0;
    }
    __syncthreads();

    // ---- stage SELF rows coalesced: warp handles one 128B row per step ----
    #pragma unroll 4
    for (int it = 0; it < NPB / 4; ++it) {
        int nd = wrp + 4 * it;
        comb[nd][lane] = feat[snid[nd] * EMB + lane];
    }
    __syncthreads();

    // ---- each thread copies its own self row to registers (float4, own row) ----
    float4 rc[16];   // [0..7]=self, [8..15]=agg
    {
        const float4* row = reinterpret_cast<const float4*>(&comb[tid][0]);
        #pragma unroll
        for (int i = 0; i < 8; i++) rc[i] = row[i];
    }
    __syncthreads();   // everyone done reading self before agg overwrites

    // ---- mean aggregation, coalesced; neighbor ids via warp shuffle ----
    #pragma unroll 2
    for (int it = 0; it < NPB / 4; ++it) {
        int nd  = wrp + 4 * it;
        int sid = snid[nd];
        int nb  = (lane < K) ? neigh[sid * K + lane] : 0;
        float s = 0.f;
        #pragma unroll
        for (int k = 0; k < K; k++) {
            int row = __shfl_sync(0xffffffffu, nb, k);
            s += feat[row * EMB + lane];
        }
        comb[nd][lane] = s * 0.1f;
    }
    __syncthreads();

    // ---- own agg row to registers ----
    {
        const float4* row = reinterpret_cast<const float4*>(&comb[tid][0]);
        #pragma unroll
        for (int i = 0; i < 8; i++) rc[8 + i] = row[i];
    }
    // Row-private from here: thread reads/writes only comb[tid][*]. No sync needed.

    // ---- matvec: out_j = relu( [self|agg] . W[j][:] ), W broadcast from smem ----
    const float4* Wv = reinterpret_cast<const float4*>(Ws);
    #pragma unroll 4
    for (int j = 0; j < 32; j++) {
        float acc = 0.f;
        #pragma unroll
        for (int i4 = 0; i4 < 16; i4++) {
            float4 w = Wv[j * 16 + i4];   // uniform address -> LDS broadcast
            float4 c = rc[i4];
            acc = fmaf(c.x, w.x, acc);
            acc = fmaf(c.y, w.y, acc);
            acc = fmaf(c.z, w.z, acc);
            acc = fmaf(c.w, w.w, acc);
        }
        comb[tid][j] = fmaxf(acc, 0.f);
    }
    __syncthreads();

    // ---- coalesced store ----
    #pragma unroll 4
    for (int it = 0; it < NPB / 4; ++it) {
        int nd = wrp + 4 * it;
        int g  = base + nd;
        if (g < n)
            out[g * EMB + lane] = comb[nd][lane];
    }
}

extern "C" void kernel_launch(void* const* d_in, const int* in_sizes, int n_in,
                              void* d_out, int out_size)
{
    // metadata order: emb, W1, W2, node_batch, neigh
    const float* emb        = (const float*)d_in[0];
    const float* W1         = (const float*)d_in[1];
    const float* W2         = (const float*)d_in[2];
    const int*   node_batch = (const int*)  d_in[3];
    const int*   neigh      = (const int*)  d_in[4];
    float*       out        = (float*)d_out;

    const int N = in_sizes[0] / EMB;   // 500000
    const int B = in_sizes[3];         // 100000

    float* h1 = nullptr;
    cudaGetSymbolAddress((void**)&h1, g_h1);

    // Layer 1: h1 = relu([emb | mean(emb[neigh])] @ W1^T) for all nodes
    sage_layer_kernel<<<(N + NPB - 1) / NPB, THREADS>>>(emb, nullptr, neigh, W1, h1, N);
    // Layer 2: out = relu([h1[nb] | mean(h1[neigh[nb]])] @ W2^T) for batch nodes
    sage_layer_kernel<<<(B + NPB - 1) / NPB, THREADS>>>(h1, node_batch, neigh, W2, out, B);
}

// round 3
// speedup vs baseline: 1.7806x; 1.5656x over previous
#include <cuda_runtime.h>
#include <cuda_bf16.h>

#define EMB 32
#define K 10
#define NPB 128      // nodes per block (32 per warp)
#define THREADS 128
#define PITCH 34     // floats per comb row: 8B-aligned rows, mild 2-way LDS conflicts

// 64 MB scratch for layer-1 hidden embeddings (allowed: __device__ global)
__device__ float g_h1[500000 * EMB];

// Packed dual-FMA: acc2 += a ⊙ b (two independent fp32 lanes) — sm_103a f32x2
__device__ __forceinline__ void ffma2(unsigned long long& acc,
                                      unsigned long long a, unsigned long long b)
{
    asm("fma.rn.f32x2 %0, %1, %2, %0;" : "+l"(acc) : "l"(a), "l"(b));
}

__global__ __launch_bounds__(THREADS, 7)
void sage_layer_kernel(const float* __restrict__ feat,      // [Nf, 32]
                       const int*   __restrict__ node_ids,  // [n] or nullptr
                       const int*   __restrict__ neigh,     // [N_NODES, K]
                       const float* __restrict__ W,         // [32, 64] row-major
                       float*       __restrict__ out,       // [n, 32]
                       int n)
{
    __shared__ __align__(16) float Ws[32 * 64];          // 8 KB
    __shared__ __align__(16) float comb[NPB * PITCH];    // 17.4 KB

    const int tid   = threadIdx.x;
    const int lane  = tid & 31;
    const int wrp   = tid >> 5;
    const int nbase = blockIdx.x * NPB + wrp * 32;   // warp's first node
    const int myrow = wrp * 32 + lane;               // this thread's comb row

    // ---- W into shared (coalesced), only block-wide sync in the kernel ----
    #pragma unroll
    for (int x = tid; x < 32 * 64; x += THREADS)
        Ws[x] = W[x];
    __syncthreads();

    // ---- this lane's node id (register, broadcast by shuffle) ----
    int g   = nbase + lane;
    int sid = (g < n) ? (node_ids ? node_ids[g] : g) : 0;

    float* crow = &comb[(wrp * 32) * PITCH];   // warp-private smem slice

    // ---- self rows: warp loads one coalesced 128B row per step ----
    #pragma unroll 4
    for (int r = 0; r < 32; r++) {
        int s = __shfl_sync(0xffffffffu, sid, r);
        crow[r * PITCH + lane] = feat[s * EMB + lane];
    }
    __syncwarp();

    // ---- own self row -> packed registers ----
    unsigned long long rc[32];   // [0..15]=self pairs, [16..31]=agg pairs
    {
        const unsigned long long* p =
            reinterpret_cast<const unsigned long long*>(&comb[myrow * PITCH]);
        #pragma unroll
        for (int i = 0; i < 16; i++) rc[i] = p[i];
    }
    __syncwarp();   // all lanes captured self before agg overwrites

    // ---- mean aggregation: pipelined id loads, 10 gathers in flight ----
    {
        int s0 = __shfl_sync(0xffffffffu, sid, 0);
        int nb = (lane < K) ? neigh[s0 * K + lane] : 0;
        #pragma unroll 2
        for (int r = 0; r < 32; r++) {
            int nb_next = 0;
            if (r < 31) {
                int s1 = __shfl_sync(0xffffffffu, sid, r + 1);
                nb_next = (lane < K) ? neigh[s1 * K + lane] : 0;  // prefetch next ids
            }
            float acc = 0.f;
            #pragma unroll
            for (int k = 0; k < K; k++) {
                int row = __shfl_sync(0xffffffffu, nb, k);
                acc += feat[row * EMB + lane];
            }
            crow[r * PITCH + lane] = acc * 0.1f;
            nb = nb_next;
        }
    }
    __syncwarp();

    // ---- own agg row -> packed registers ----
    {
        const unsigned long long* p =
            reinterpret_cast<const unsigned long long*>(&comb[myrow * PITCH]);
        #pragma unroll
        for (int i = 0; i < 16; i++) rc[16 + i] = p[i];
    }
    // Thread-private from here (no warp exchange until store staging).

    // ---- matvec with packed dual-FMA: out_j = relu([self|agg] . W[j]) ----
    const ulonglong2* Wp = reinterpret_cast<const ulonglong2*>(Ws);
    #pragma unroll 4
    for (int j = 0; j < 32; j++) {
        unsigned long long acc2 = 0ull;          // packed (0.f, 0.f)
        #pragma unroll
        for (int i2 = 0; i2 < 16; i2++) {
            ulonglong2 w = Wp[j * 16 + i2];      // uniform LDS.128 broadcast
            ffma2(acc2, rc[2 * i2],     w.x);
            ffma2(acc2, rc[2 * i2 + 1], w.y);
        }
        float lo, hi;
        asm("mov.b64 {%0, %1}, %2;" : "=f"(lo), "=f"(hi) : "l"(acc2));
        comb[myrow * PITCH + j] = fmaxf(lo + hi, 0.f);
    }
    __syncwarp();

    // ---- coalesced store of warp's 32 output rows ----
    #pragma unroll 4
    for (int r = 0; r < 32; r++) {
        int gg = nbase + r;
        if (gg < n)
            out[gg * EMB + lane] = crow[r * PITCH + lane];
    }
}

extern "C" void kernel_launch(void* const* d_in, const int* in_sizes, int n_in,
                              void* d_out, int out_size)
{
    // metadata order: emb, W1, W2, node_batch, neigh
    const float* emb        = (const float*)d_in[0];
    const float* W1         = (const float*)d_in[1];
    const float* W2         = (const float*)d_in[2];
    const int*   node_batch = (const int*)  d_in[3];
    const int*   neigh      = (const int*)  d_in[4];
    float*       out        = (float*)d_out;

    const int N = in_sizes[0] / EMB;   // 500000
    const int B = in_sizes[3];         // 100000

    float* h1 = nullptr;
    cudaGetSymbolAddress((void**)&h1, g_h1);

    // Layer 1: h1 = relu([emb | mean(emb[neigh])] @ W1^T) for all nodes
    sage_layer_kernel<<<(N + NPB - 1) / NPB, THREADS>>>(emb, nullptr, neigh, W1, h1, N);
    // Layer 2: out = relu([h1[nb] | mean(h1[neigh[nb]])] @ W2^T) for batch nodes
    sage_layer_kernel<<<(B + NPB - 1) / NPB, THREADS>>>(h1, node_batch, neigh, W2, out, B);
}

// round 4
// speedup vs baseline: 1.9388x; 1.0889x over previous
#include <cuda_runtime.h>
#include <cuda_bf16.h>

#define EMB 32
#define K 10
#define NPB 128      // nodes per block (32 per warp)
#define THREADS 128
#define PITCH 36     // floats per comb row: 144B rows -> 16B aligned, conflict-free

// 64 MB scratch for layer-1 hidden embeddings (allowed: __device__ global)
__device__ float g_h1[500000 * EMB];

// sm_103a packed fp32 pair ops
__device__ __forceinline__ void ffma2(unsigned long long& acc,
                                      unsigned long long a, unsigned long long b)
{ asm("fma.rn.f32x2 %0, %1, %2, %0;" : "+l"(acc) : "l"(a), "l"(b)); }

__device__ __forceinline__ void fadd2(unsigned long long& a, unsigned long long b)
{ asm("add.rn.f32x2 %0, %0, %1;" : "+l"(a) : "l"(b)); }

__device__ __forceinline__ void fmul2(unsigned long long& a, unsigned long long b)
{ asm("mul.rn.f32x2 %0, %0, %1;" : "+l"(a) : "l"(b)); }

__device__ __forceinline__ unsigned long long pack2(float lo, float hi)
{ unsigned long long r; asm("mov.b64 %0, {%1, %2};" : "=l"(r) : "f"(lo), "f"(hi)); return r; }

__global__ __launch_bounds__(THREADS, 7)
void sage_layer_kernel(const float* __restrict__ feat,      // [Nf, 32]
                       const int*   __restrict__ node_ids,  // [n] or nullptr
                       const int*   __restrict__ neigh,     // [N_NODES, K]
                       const float* __restrict__ W,         // [32, 64] row-major
                       float*       __restrict__ out,       // [n, 32]
                       int n)
{
    __shared__ __align__(16) float Ws[32 * 64];          // 8 KB
    __shared__ __align__(16) float comb[NPB * PITCH];    // 18.4 KB

    const int tid   = threadIdx.x;
    const int lane  = tid & 31;
    const int wrp   = tid >> 5;
    const int grp   = lane >> 3;        // 4 row-groups per warp
    const int c4    = lane & 7;         // float4 column within row
    const int nbase = blockIdx.x * NPB + wrp * 32;
    const int myrow = wrp * 32 + lane;

    // ---- W into shared (coalesced); only block-wide sync in the kernel ----
    #pragma unroll
    for (int x = tid; x < 32 * 64; x += THREADS)
        Ws[x] = W[x];
    __syncthreads();

    // ---- this lane's node id (kept in a register, broadcast by shuffle) ----
    int g   = nbase + lane;
    int sid = (g < n) ? (node_ids ? node_ids[g] : g) : 0;

    float* crow = &comb[(wrp * 32) * PITCH];   // warp-private smem slice
    const unsigned long long sc2 = pack2(0.1f, 0.1f);

    // ======== PHASE 1: mean aggregation (4 rows per LDG.128) ========
    #pragma unroll 2
    for (int it = 0; it < 8; ++it) {
        int nd   = 4 * it + grp;                        // node this group handles
        int sidg = __shfl_sync(0xffffffffu, sid, nd);
        int nb[K];
        #pragma unroll
        for (int k = 0; k < K; k++)                     // 10 broadcast id loads (L1)
            nb[k] = neigh[sidg * K + k];
        unsigned long long ax = 0ull, ay = 0ull;        // packed (0,0)
        #pragma unroll
        for (int k = 0; k < K; k++) {                   // 10 independent 4-line loads
            ulonglong2 v = *reinterpret_cast<const ulonglong2*>(
                               &feat[nb[k] * EMB + c4 * 4]);
            fadd2(ax, v.x);
            fadd2(ay, v.y);
        }
        fmul2(ax, sc2);
        fmul2(ay, sc2);
        *reinterpret_cast<ulonglong2*>(&crow[nd * PITCH + c4 * 4])
            = make_ulonglong2(ax, ay);
    }
    __syncwarp();

    // ---- own agg row -> packed registers ----
    unsigned long long rc[32];   // [0..15]=self pairs, [16..31]=agg pairs
    {
        const unsigned long long* p =
            reinterpret_cast<const unsigned long long*>(&comb[myrow * PITCH]);
        #pragma unroll
        for (int i = 0; i < 16; i++) rc[16 + i] = p[i];
    }
    __syncwarp();

    // ======== PHASE 2: self rows (4 rows per LDG.128) ========
    #pragma unroll 2
    for (int it = 0; it < 8; ++it) {
        int nd = 4 * it + grp;
        int s  = __shfl_sync(0xffffffffu, sid, nd);
        ulonglong2 v = *reinterpret_cast<const ulonglong2*>(
                           &feat[s * EMB + c4 * 4]);
        *reinterpret_cast<ulonglong2*>(&crow[nd * PITCH + c4 * 4]) = v;
    }
    __syncwarp();
    {
        const unsigned long long* p =
            reinterpret_cast<const unsigned long long*>(&comb[myrow * PITCH]);
        #pragma unroll
        for (int i = 0; i < 16; i++) rc[i] = p[i];
    }
    // Thread-private from here.

    // ======== PHASE 3: matvec, packed dual-FMA ========
    const ulonglong2* Wp = reinterpret_cast<const ulonglong2*>(Ws);
    #pragma unroll 4
    for (int j = 0; j < 32; j++) {
        unsigned long long acc2 = 0ull;
        #pragma unroll
        for (int i2 = 0; i2 < 16; i2++) {
            ulonglong2 w = Wp[j * 16 + i2];      // uniform LDS.128 broadcast
            ffma2(acc2, rc[2 * i2],     w.x);
            ffma2(acc2, rc[2 * i2 + 1], w.y);
        }
        float lo, hi;
        asm("mov.b64 {%0, %1}, %2;" : "=f"(lo), "=f"(hi) : "l"(acc2));
        comb[myrow * PITCH + j] = fmaxf(lo + hi, 0.f);
    }
    __syncwarp();

    // ======== PHASE 4: coalesced store (4 rows per STG.128) ========
    #pragma unroll
    for (int it = 0; it < 8; ++it) {
        int nd = 4 * it + grp;
        int gg = nbase + nd;
        if (gg < n) {
            float4 v = *reinterpret_cast<const float4*>(&crow[nd * PITCH + c4 * 4]);
            *reinterpret_cast<float4*>(&out[gg * EMB + c4 * 4]) = v;
        }
    }
}

extern "C" void kernel_launch(void* const* d_in, const int* in_sizes, int n_in,
                              void* d_out, int out_size)
{
    // metadata order: emb, W1, W2, node_batch, neigh
    const float* emb        = (const float*)d_in[0];
    const float* W1         = (const float*)d_in[1];
    const float* W2         = (const float*)d_in[2];
    const int*   node_batch = (const int*)  d_in[3];
    const int*   neigh      = (const int*)  d_in[4];
    float*       out        = (float*)d_out;

    const int N = in_sizes[0] / EMB;   // 500000
    const int B = in_sizes[3];         // 100000

    float* h1 = nullptr;
    cudaGetSymbolAddress((void**)&h1, g_h1);

    // Layer 1: h1 = relu([emb | mean(emb[neigh])] @ W1^T) for all nodes
    sage_layer_kernel<<<(N + NPB - 1) / NPB, THREADS>>>(emb, nullptr, neigh, W1, h1, N);
    // Layer 2: out = relu([h1[nb] | mean(h1[neigh[nb]])] @ W2^T) for batch nodes
    sage_layer_kernel<<<(B + NPB - 1) / NPB, THREADS>>>(h1, node_batch, neigh, W2, out, B);
}